// round 5
// baseline (speedup 1.0000x reference)
#include <cuda_runtime.h>

#define NW       16384
#define MAXLEN   16
#define EMBD     64
#define HIDD     256
#define BW       64          // words per block
#define NTHREADS 512
#define KT       16          // K-tile per stage
#define NST_X    4           // 64/16 stages over x-part
#define NST_H    16          // 256/16 stages over h-part
#define NST      (NST_X + NST_H)

// smem (floats): h double buffer + c + x_t + W double-buffer stage + lengths
#define SMEM_FLOATS (2*BW*HIDD + BW*HIDD + BW*EMBD + 2*KT*128)
#define SMEM_BYTES  (SMEM_FLOATS*4 + BW*4)

__device__ __forceinline__ float fsigm(float x) {
    return __fdividef(1.0f, 1.0f + __expf(-x));
}
__device__ __forceinline__ float ftanh_(float x) {
    return __fdividef(2.0f, 1.0f + __expf(-2.0f * x)) - 1.0f;
}

__global__ __launch_bounds__(NTHREADS, 1)
void bilstm_kernel(const int*   __restrict__ char_ids,
                   const int*   __restrict__ lengths,
                   const float* __restrict__ emb,
                   const float* __restrict__ Wih_f, const float* __restrict__ Whh_f,
                   const float* __restrict__ bih_f, const float* __restrict__ bhh_f,
                   const float* __restrict__ Wih_b, const float* __restrict__ Whh_b,
                   const float* __restrict__ bih_b, const float* __restrict__ bhh_b,
                   float* __restrict__ out)
{
    extern __shared__ float sm[];
    float* h_s  = sm;                    // [2][BW][HIDD]
    float* c_s  = h_s + 2*BW*HIDD;       // [BW][HIDD]
    float* xt_s = c_s + BW*HIDD;         // [BW][EMBD]
    float* W_s  = xt_s + BW*EMBD;        // [2][KT][128]
    int*   len_s = (int*)(W_s + 2*KT*128);  // [BW]

    const int tid  = threadIdx.x;
    const int lane = tid & 31;
    const int warp = tid >> 5;           // 16 warps, each owns 4 words
    const int dir  = blockIdx.y;
    const int w0   = blockIdx.x * BW;

    const float* Wih = dir ? Wih_b : Wih_f;
    const float* Whh = dir ? Whh_b : Whh_f;
    const float* bih = dir ? bih_b : bih_f;
    const float* bhh = dir ? bhh_b : bhh_f;

    // ---- init ----
    for (int i = tid; i < BW; i += NTHREADS) len_s[i] = lengths[w0 + i];
    for (int i = tid; i < 2*BW*HIDD; i += NTHREADS) h_s[i] = 0.0f;
    for (int i = tid; i < BW*HIDD;   i += NTHREADS) c_s[i] = 0.0f;
    __syncthreads();

    // weight-staging constants: 128 rows (4 gates x 32 hid of current chunk),
    // each thread stages 4 consecutive k values of one row (one float4)
    const int rIdx = tid & 127;          // staged row index within chunk
    const int kh   = tid >> 7;           // 0..3 -> k sub-offset
    const int g_st = rIdx >> 5;
    const int i_st = rIdx & 31;

    int cur = 0;
    for (int t = 0; t < MAXLEN; ++t) {
        // ---- gather x_t (embedding lookup, reversed+clipped for backward) ----
        for (int idx = tid; idx < BW*EMBD; idx += NTHREADS) {
            int w = idx >> 6, e = idx & 63;
            int L = len_s[w];
            int te = dir ? max(L - 1 - t, 0) : t;
            int ch = char_ids[(w0 + w)*MAXLEN + te];
            xt_s[idx] = emb[ch*EMBD + e];
        }
        __syncthreads();

        const float* hc = h_s + cur*(BW*HIDD);
        float*       hn = h_s + (cur^1)*(BW*HIDD);

        for (int chunk = 0; chunk < 8; ++chunk) {
            const int j0 = chunk * 32;
            const int row_st = g_st*HIDD + j0 + i_st;   // global weight row for staging

            // accumulators: [gate][word], init with bias (b_ih + b_hh)
            float acc0[4], acc1[4], acc2[4], acc3[4];
            {
                int j = j0 + lane;
                float b0 = bih[j]          + bhh[j];
                float b1 = bih[HIDD + j]   + bhh[HIDD + j];
                float b2 = bih[2*HIDD + j] + bhh[2*HIDD + j];
                float b3 = bih[3*HIDD + j] + bhh[3*HIDD + j];
                #pragma unroll
                for (int wi = 0; wi < 4; ++wi) {
                    acc0[wi] = b0; acc1[wi] = b1; acc2[wi] = b2; acc3[wi] = b3;
                }
            }

            // prefetch stage 0 (x-part weights)
            float4 pf = *(const float4*)(Wih + row_st*EMBD + kh*4);

            for (int s = 0; s < NST; ++s) {
                // commit prefetched tile to smem buffer s&1
                float* wb = W_s + (s & 1)*(KT*128);
                const int kloc = kh * 4;
                wb[(kloc+0)*128 + rIdx] = pf.x;
                wb[(kloc+1)*128 + rIdx] = pf.y;
                wb[(kloc+2)*128 + rIdx] = pf.z;
                wb[(kloc+3)*128 + rIdx] = pf.w;
                __syncthreads();

                // prefetch next stage (overlaps with compute below)
                int sn = s + 1;
                if (sn < NST) {
                    if (sn < NST_X)
                        pf = *(const float4*)(Wih + row_st*EMBD + sn*KT + kh*4);
                    else
                        pf = *(const float4*)(Whh + row_st*HIDD + (sn - NST_X)*KT + kh*4);
                }

                // A-operand row pointers for this stage (warp-uniform -> smem broadcast)
                const float *ar0, *ar1, *ar2, *ar3;
                if (s < NST_X) {
                    const float* base = xt_s + s*KT;
                    ar0 = base + (warp*4+0)*EMBD; ar1 = base + (warp*4+1)*EMBD;
                    ar2 = base + (warp*4+2)*EMBD; ar3 = base + (warp*4+3)*EMBD;
                } else {
                    const float* base = hc + (s - NST_X)*KT;
                    ar0 = base + (warp*4+0)*HIDD; ar1 = base + (warp*4+1)*HIDD;
                    ar2 = base + (warp*4+2)*HIDD; ar3 = base + (warp*4+3)*HIDD;
                }

                #pragma unroll
                for (int kk = 0; kk < KT; ++kk) {
                    float wv0 = wb[kk*128       + lane];
                    float wv1 = wb[kk*128 +  32 + lane];
                    float wv2 = wb[kk*128 +  64 + lane];
                    float wv3 = wb[kk*128 +  96 + lane];
                    float a0 = ar0[kk], a1 = ar1[kk], a2 = ar2[kk], a3 = ar3[kk];
                    acc0[0] = fmaf(a0, wv0, acc0[0]); acc1[0] = fmaf(a0, wv1, acc1[0]);
                    acc2[0] = fmaf(a0, wv2, acc2[0]); acc3[0] = fmaf(a0, wv3, acc3[0]);
                    acc0[1] = fmaf(a1, wv0, acc0[1]); acc1[1] = fmaf(a1, wv1, acc1[1]);
                    acc2[1] = fmaf(a1, wv2, acc2[1]); acc3[1] = fmaf(a1, wv3, acc3[1]);
                    acc0[2] = fmaf(a2, wv0, acc0[2]); acc1[2] = fmaf(a2, wv1, acc1[2]);
                    acc2[2] = fmaf(a2, wv2, acc2[2]); acc3[2] = fmaf(a2, wv3, acc3[2]);
                    acc0[3] = fmaf(a3, wv0, acc0[3]); acc1[3] = fmaf(a3, wv1, acc1[3]);
                    acc2[3] = fmaf(a3, wv2, acc2[3]); acc3[3] = fmaf(a3, wv3, acc3[3]);
                }
            }

            // ---- LSTM cell update for this chunk's (word, hid) elements ----
            {
                int j = j0 + lane;
                #pragma unroll
                for (int wi = 0; wi < 4; ++wi) {
                    int w = warp*4 + wi;
                    float iv = fsigm(acc0[wi]);
                    float fv = fsigm(acc1[wi]);
                    float gv = ftanh_(acc2[wi]);
                    float ov = fsigm(acc3[wi]);
                    float cold = c_s[w*HIDD + j];
                    float cnew = fmaf(fv, cold, iv * gv);
                    float hnew = ov * ftanh_(cnew);
                    bool m = (t < len_s[w]);
                    c_s[w*HIDD + j] = m ? cnew : cold;
                    hn[w*HIDD + j]  = m ? hnew : hc[w*HIDD + j];
                }
            }
        }
        cur ^= 1;
        __syncthreads();
    }

    // ---- write final h (concat layout: [w, dir*256 + j]) ----
    const float* hf = h_s + cur*(BW*HIDD);
    for (int idx = tid; idx < BW*HIDD; idx += NTHREADS) {
        int w = idx >> 8, j = idx & 255;
        out[(w0 + w)*(2*HIDD) + dir*HIDD + j] = hf[idx];
    }
}

extern "C" void kernel_launch(void* const* d_in, const int* in_sizes, int n_in,
                              void* d_out, int out_size)
{
    const int*   char_ids = (const int*)  d_in[0];
    const int*   lengths  = (const int*)  d_in[1];
    const float* emb      = (const float*)d_in[2];
    const float* Wih_f    = (const float*)d_in[3];
    const float* Whh_f    = (const float*)d_in[4];
    const float* bih_f    = (const float*)d_in[5];
    const float* bhh_f    = (const float*)d_in[6];
    const float* Wih_b    = (const float*)d_in[7];
    const float* Whh_b    = (const float*)d_in[8];
    const float* bih_b    = (const float*)d_in[9];
    const float* bhh_b    = (const float*)d_in[10];
    float* out = (float*)d_out;

    cudaFuncSetAttribute(bilstm_kernel,
                         cudaFuncAttributeMaxDynamicSharedMemorySize, SMEM_BYTES);

    dim3 grid(NW / BW, 2);
    bilstm_kernel<<<grid, NTHREADS, SMEM_BYTES>>>(
        char_ids, lengths, emb,
        Wih_f, Whh_f, bih_f, bhh_f,
        Wih_b, Whh_b, bih_b, bhh_b,
        out);
}

// round 10
// speedup vs baseline: 1.0371x; 1.0371x over previous
#include <cuda_runtime.h>

#define NW       16384
#define MAXLEN   16
#define EMBD     64
#define HIDD     256
#define BW       64          // words per block
#define NTHREADS 512
#define KT       16          // K-tile per stage
#define NST_X    4           // 64/16 stages over x-part
#define NST_H    16          // 256/16 stages over h-part
#define NST      (NST_X + NST_H)

// smem (floats): h double buffer + c + x_t + W double-buffer stage + lengths
#define SMEM_FLOATS (2*BW*HIDD + BW*HIDD + BW*EMBD + 2*KT*128)
#define SMEM_BYTES  (SMEM_FLOATS*4 + BW*4)

__device__ __forceinline__ float fsigm(float x) {
    return __fdividef(1.0f, 1.0f + __expf(-x));
}
__device__ __forceinline__ float ftanh_(float x) {
    return __fdividef(2.0f, 1.0f + __expf(-2.0f * x)) - 1.0f;
}

// ---- fp32x2 (FFMA2) helpers: only reachable via PTX, ptxas never auto-fuses ----
__device__ __forceinline__ unsigned long long pk2(float lo, float hi) {
    unsigned long long r;
    asm("mov.b64 %0, {%1, %2};" : "=l"(r) : "f"(lo), "f"(hi));
    return r;
}
__device__ __forceinline__ unsigned long long dup2(float v) {
    unsigned long long r;
    asm("mov.b64 %0, {%1, %1};" : "=l"(r) : "f"(v));
    return r;
}
__device__ __forceinline__ void fma2(unsigned long long& acc,
                                     unsigned long long a,
                                     unsigned long long b) {
    asm("fma.rn.f32x2 %0, %1, %2, %0;" : "+l"(acc) : "l"(a), "l"(b));
}
__device__ __forceinline__ void upk2(float& lo, float& hi, unsigned long long v) {
    asm("mov.b64 {%0, %1}, %2;" : "=f"(lo), "=f"(hi) : "l"(v));
}

// One k-step: LDS.128 pulls (i,f,g,o) weight quad for this lane; two FFMA2 per word.
#define GSTEP(KK, AV0, AV1, AV2, AV3)                                          \
    {                                                                          \
        const ulonglong2 wp =                                                  \
            *(const ulonglong2*)(wb + (KK)*128 + lane4);                       \
        unsigned long long ad;                                                 \
        ad = dup2(AV0); fma2(accIF[0], ad, wp.x); fma2(accGO[0], ad, wp.y);    \
        ad = dup2(AV1); fma2(accIF[1], ad, wp.x); fma2(accGO[1], ad, wp.y);    \
        ad = dup2(AV2); fma2(accIF[2], ad, wp.x); fma2(accGO[2], ad, wp.y);    \
        ad = dup2(AV3); fma2(accIF[3], ad, wp.x); fma2(accGO[3], ad, wp.y);    \
    }

__global__ __launch_bounds__(NTHREADS, 1)
void bilstm_kernel(const int*   __restrict__ char_ids,
                   const int*   __restrict__ lengths,
                   const float* __restrict__ emb,
                   const float* __restrict__ Wih_f, const float* __restrict__ Whh_f,
                   const float* __restrict__ bih_f, const float* __restrict__ bhh_f,
                   const float* __restrict__ Wih_b, const float* __restrict__ Whh_b,
                   const float* __restrict__ bih_b, const float* __restrict__ bhh_b,
                   float* __restrict__ out)
{
    extern __shared__ float sm[];
    float* h_s  = sm;                    // [2][BW][HIDD]
    float* c_s  = h_s + 2*BW*HIDD;       // [BW][HIDD]
    float* xt_s = c_s + BW*HIDD;         // [BW][EMBD]
    float* W_s  = xt_s + BW*EMBD;        // [2][KT][32 lanes][4 gates]
    int*   len_s = (int*)(W_s + 2*KT*128);  // [BW]

    const int tid   = threadIdx.x;
    const int lane  = tid & 31;
    const int lane4 = lane * 4;
    const int warp  = tid >> 5;          // 16 warps, each owns 4 words
    const int dir   = blockIdx.y;
    const int w0    = blockIdx.x * BW;

    const float* Wih = dir ? Wih_b : Wih_f;
    const float* Whh = dir ? Whh_b : Whh_f;
    const float* bih = dir ? bih_b : bih_f;
    const float* bhh = dir ? bhh_b : bhh_f;

    // ---- init ----
    for (int i = tid; i < BW; i += NTHREADS) len_s[i] = lengths[w0 + i];
    for (int i = tid; i < 2*BW*HIDD; i += NTHREADS) h_s[i] = 0.0f;
    for (int i = tid; i < BW*HIDD;   i += NTHREADS) c_s[i] = 0.0f;
    __syncthreads();

    // weight-staging constants: 128 rows (4 gates x 32 hid of current chunk),
    // each thread stages 4 consecutive k values of one row (one float4)
    const int rIdx = tid & 127;          // staged row index within chunk
    const int kh   = tid >> 7;           // 0..3 -> k sub-offset
    const int g_st = rIdx >> 5;
    const int i_st = rIdx & 31;
    const int sBase = i_st*4 + g_st;     // smem column in [lane][gate] layout

    int cur = 0;
    for (int t = 0; t < MAXLEN; ++t) {
        // ---- gather x_t (embedding lookup, reversed+clipped for backward) ----
        for (int idx = tid; idx < BW*EMBD; idx += NTHREADS) {
            int w = idx >> 6, e = idx & 63;
            int L = len_s[w];
            int te = dir ? max(L - 1 - t, 0) : t;
            int ch = char_ids[(w0 + w)*MAXLEN + te];
            xt_s[idx] = emb[ch*EMBD + e];
        }
        __syncthreads();

        const float* hc = h_s + cur*(BW*HIDD);
        float*       hn = h_s + (cur^1)*(BW*HIDD);

        for (int chunk = 0; chunk < 8; ++chunk) {
            const int j0 = chunk * 32;
            const int row_st = g_st*HIDD + j0 + i_st;   // global weight row staged

            // accumulators: fp32x2 pairs, (i,f) and (g,o) per word, bias-init
            unsigned long long accIF[4], accGO[4];
            {
                int j = j0 + lane;
                float b0 = bih[j]          + bhh[j];
                float b1 = bih[HIDD + j]   + bhh[HIDD + j];
                float b2 = bih[2*HIDD + j] + bhh[2*HIDD + j];
                float b3 = bih[3*HIDD + j] + bhh[3*HIDD + j];
                unsigned long long bIF = pk2(b0, b1);
                unsigned long long bGO = pk2(b2, b3);
                #pragma unroll
                for (int wi = 0; wi < 4; ++wi) { accIF[wi] = bIF; accGO[wi] = bGO; }
            }

            // prefetch stage 0 (x-part weights)
            float4 pf = *(const float4*)(Wih + row_st*EMBD + kh*4);

            for (int s = 0; s < NST; ++s) {
                // commit prefetched tile to smem buffer s&1, [k][lane][gate] layout
                float* wb = W_s + (s & 1)*(KT*128);
                const int kloc = kh * 4;
                wb[(kloc+0)*128 + sBase] = pf.x;
                wb[(kloc+1)*128 + sBase] = pf.y;
                wb[(kloc+2)*128 + sBase] = pf.z;
                wb[(kloc+3)*128 + sBase] = pf.w;
                __syncthreads();

                // prefetch next stage (overlaps with compute below)
                int sn = s + 1;
                if (sn < NST) {
                    if (sn < NST_X)
                        pf = *(const float4*)(Wih + row_st*EMBD + sn*KT + kh*4);
                    else
                        pf = *(const float4*)(Whh + row_st*HIDD + (sn - NST_X)*KT + kh*4);
                }

                // A-operand row pointers for this stage (warp-uniform -> smem broadcast)
                const float *ar0, *ar1, *ar2, *ar3;
                if (s < NST_X) {
                    const float* base = xt_s + s*KT;
                    ar0 = base + (warp*4+0)*EMBD; ar1 = base + (warp*4+1)*EMBD;
                    ar2 = base + (warp*4+2)*EMBD; ar3 = base + (warp*4+3)*EMBD;
                } else {
                    const float* base = hc + (s - NST_X)*KT;
                    ar0 = base + (warp*4+0)*HIDD; ar1 = base + (warp*4+1)*HIDD;
                    ar2 = base + (warp*4+2)*HIDD; ar3 = base + (warp*4+3)*HIDD;
                }

                #pragma unroll
                for (int k2 = 0; k2 < KT/2; ++k2) {
                    float2 a0 = *(const float2*)(ar0 + 2*k2);
                    float2 a1 = *(const float2*)(ar1 + 2*k2);
                    float2 a2 = *(const float2*)(ar2 + 2*k2);
                    float2 a3 = *(const float2*)(ar3 + 2*k2);
                    GSTEP(2*k2,     a0.x, a1.x, a2.x, a3.x);
                    GSTEP(2*k2 + 1, a0.y, a1.y, a2.y, a3.y);
                }
            }

            // ---- LSTM cell update for this chunk's (word, hid) elements ----
            {
                int j = j0 + lane;
                #pragma unroll
                for (int wi = 0; wi < 4; ++wi) {
                    int w = warp*4 + wi;
                    float vi, vf, vg, vo;
                    upk2(vi, vf, accIF[wi]);
                    upk2(vg, vo, accGO[wi]);
                    float iv = fsigm(vi);
                    float fv = fsigm(vf);
                    float gv = ftanh_(vg);
                    float ov = fsigm(vo);
                    float cold = c_s[w*HIDD + j];
                    float cnew = fmaf(fv, cold, iv * gv);
                    float hnew = ov * ftanh_(cnew);
                    bool m = (t < len_s[w]);
                    c_s[w*HIDD + j] = m ? cnew : cold;
                    hn[w*HIDD + j]  = m ? hnew : hc[w*HIDD + j];
                }
            }
        }
        cur ^= 1;
        __syncthreads();
    }

    // ---- write final h (concat layout: [w, dir*256 + j]) ----
    const float* hf = h_s + cur*(BW*HIDD);
    for (int idx = tid; idx < BW*HIDD; idx += NTHREADS) {
        int w = idx >> 8, j = idx & 255;
        out[(w0 + w)*(2*HIDD) + dir*HIDD + j] = hf[idx];
    }
}

extern "C" void kernel_launch(void* const* d_in, const int* in_sizes, int n_in,
                              void* d_out, int out_size)
{
    const int*   char_ids = (const int*)  d_in[0];
    const int*   lengths  = (const int*)  d_in[1];
    const float* emb      = (const float*)d_in[2];
    const float* Wih_f    = (const float*)d_in[3];
    const float* Whh_f    = (const float*)d_in[4];
    const float* bih_f    = (const float*)d_in[5];
    const float* bhh_f    = (const float*)d_in[6];
    const float* Wih_b    = (const float*)d_in[7];
    const float* Whh_b    = (const float*)d_in[8];
    const float* bih_b    = (const float*)d_in[9];
    const float* bhh_b    = (const float*)d_in[10];
    float* out = (float*)d_out;

    cudaFuncSetAttribute(bilstm_kernel,
                         cudaFuncAttributeMaxDynamicSharedMemorySize, SMEM_BYTES);

    dim3 grid(NW / BW, 2);
    bilstm_kernel<<<grid, NTHREADS, SMEM_BYTES>>>(
        char_ids, lengths, emb,
        Wih_f, Whh_f, bih_f, bhh_f,
        Wih_b, Whh_b, bih_b, bhh_b,
        out);
}

// round 14
// speedup vs baseline: 1.0380x; 1.0009x over previous
#include <cuda_runtime.h>

#define NW       16384
#define MAXLEN   16
#define EMBD     64
#define HIDD     256
#define BW       64          // words per block
#define NTHREADS 512
#define KT       16          // K-tile per stage
#define NST_X    4           // 64/16 stages over x-part
#define NST_H    16          // 256/16 stages over h-part
#define NST      (NST_X + NST_H)

// smem (floats): h double buffer + c + x_t + W double-buffer stage + lengths
#define SMEM_FLOATS (2*BW*HIDD + BW*HIDD + BW*EMBD + 2*KT*128)
#define SMEM_BYTES  (SMEM_FLOATS*4 + BW*4)

__device__ __forceinline__ float fsigm(float x) {
    return __fdividef(1.0f, 1.0f + __expf(-x));
}
__device__ __forceinline__ float ftanh_(float x) {
    return __fdividef(2.0f, 1.0f + __expf(-2.0f * x)) - 1.0f;
}

// ---- fp32x2 (FFMA2) helpers: only reachable via PTX, ptxas never auto-fuses ----
__device__ __forceinline__ unsigned long long pk2(float lo, float hi) {
    unsigned long long r;
    asm("mov.b64 %0, {%1, %2};" : "=l"(r) : "f"(lo), "f"(hi));
    return r;
}
__device__ __forceinline__ unsigned long long dup2(float v) {
    unsigned long long r;
    asm("mov.b64 %0, {%1, %1};" : "=l"(r) : "f"(v));
    return r;
}
__device__ __forceinline__ void fma2(unsigned long long& acc,
                                     unsigned long long a,
                                     unsigned long long b) {
    asm("fma.rn.f32x2 %0, %1, %2, %0;" : "+l"(acc) : "l"(a), "l"(b));
}
__device__ __forceinline__ void upk2(float& lo, float& hi, unsigned long long v) {
    asm("mov.b64 {%0, %1}, %2;" : "=f"(lo), "=f"(hi) : "l"(v));
}

// One k-step: LDS.128 pulls (i,f,g,o) weight quad for this lane; two FFMA2 per word.
#define GSTEP(KK, AV0, AV1, AV2, AV3)                                          \
    {                                                                          \
        const ulonglong2 wp =                                                  \
            *(const ulonglong2*)(wb + (KK)*128 + lane4);                       \
        unsigned long long ad;                                                 \
        ad = dup2(AV0); fma2(accIF[0], ad, wp.x); fma2(accGO[0], ad, wp.y);    \
        ad = dup2(AV1); fma2(accIF[1], ad, wp.x); fma2(accGO[1], ad, wp.y);    \
        ad = dup2(AV2); fma2(accIF[2], ad, wp.x); fma2(accGO[2], ad, wp.y);    \
        ad = dup2(AV3); fma2(accIF[3], ad, wp.x); fma2(accGO[3], ad, wp.y);    \
    }

__global__ __launch_bounds__(NTHREADS, 1)
void bilstm_kernel(const int*   __restrict__ char_ids,
                   const int*   __restrict__ lengths,
                   const float* __restrict__ emb,
                   const float* __restrict__ Wih_f, const float* __restrict__ Whh_f,
                   const float* __restrict__ bih_f, const float* __restrict__ bhh_f,
                   const float* __restrict__ Wih_b, const float* __restrict__ Whh_b,
                   const float* __restrict__ bih_b, const float* __restrict__ bhh_b,
                   float* __restrict__ out)
{
    extern __shared__ float sm[];
    float* h_s  = sm;                    // [2][BW][HIDD]
    float* c_s  = h_s + 2*BW*HIDD;       // [BW][HIDD]
    float* xt_s = c_s + BW*HIDD;         // [BW][EMBD]
    float* W_s  = xt_s + BW*EMBD;        // [2][KT][32 lanes][4 gates]
    int*   len_s = (int*)(W_s + 2*KT*128);  // [BW]

    const int tid   = threadIdx.x;
    const int lane  = tid & 31;
    const int lane4 = lane * 4;
    const int warp  = tid >> 5;          // 16 warps, each owns 4 words
    const int dir   = blockIdx.y;
    const int w0    = blockIdx.x * BW;

    const float* Wih = dir ? Wih_b : Wih_f;
    const float* Whh = dir ? Whh_b : Whh_f;
    const float* bih = dir ? bih_b : bih_f;
    const float* bhh = dir ? bhh_b : bhh_f;

    // ---- init ----
    for (int i = tid; i < BW; i += NTHREADS) len_s[i] = lengths[w0 + i];
    for (int i = tid; i < 2*BW*HIDD; i += NTHREADS) h_s[i] = 0.0f;
    for (int i = tid; i < BW*HIDD;   i += NTHREADS) c_s[i] = 0.0f;
    __syncthreads();

    // weight-staging constants: 128 rows (4 gates x 32 hid of current chunk),
    // each thread stages 4 consecutive k values of one row (one float4)
    const int rIdx = tid & 127;          // staged row index within chunk
    const int kh   = tid >> 7;           // 0..3 -> k sub-offset
    const int g_st = rIdx >> 5;
    const int i_st = rIdx & 31;
    const int sBase = i_st*4 + g_st;     // smem column in [lane][gate] layout

    int cur = 0;
    for (int t = 0; t < MAXLEN; ++t) {
        // ---- gather x_t (embedding lookup, reversed+clipped for backward) ----
        for (int idx = tid; idx < BW*EMBD; idx += NTHREADS) {
            int w = idx >> 6, e = idx & 63;
            int L = len_s[w];
            int te = dir ? max(L - 1 - t, 0) : t;
            int ch = char_ids[(w0 + w)*MAXLEN + te];
            xt_s[idx] = emb[ch*EMBD + e];
        }
        __syncthreads();

        const float* hc = h_s + cur*(BW*HIDD);
        float*       hn = h_s + (cur^1)*(BW*HIDD);

        for (int chunk = 0; chunk < 8; ++chunk) {
            const int j0 = chunk * 32;
            const int row_st = g_st*HIDD + j0 + i_st;   // global weight row staged

            // accumulators: fp32x2 pairs, (i,f) and (g,o) per word, bias-init
            unsigned long long accIF[4], accGO[4];
            {
                int j = j0 + lane;
                float b0 = bih[j]          + bhh[j];
                float b1 = bih[HIDD + j]   + bhh[HIDD + j];
                float b2 = bih[2*HIDD + j] + bhh[2*HIDD + j];
                float b3 = bih[3*HIDD + j] + bhh[3*HIDD + j];
                unsigned long long bIF = pk2(b0, b1);
                unsigned long long bGO = pk2(b2, b3);
                #pragma unroll
                for (int wi = 0; wi < 4; ++wi) { accIF[wi] = bIF; accGO[wi] = bGO; }
            }

            // prefetch stage 0 (x-part weights)
            float4 pf = *(const float4*)(Wih + row_st*EMBD + kh*4);

            for (int s = 0; s < NST; ++s) {
                // commit prefetched tile to smem buffer s&1, [k][lane][gate] layout
                float* wb = W_s + (s & 1)*(KT*128);
                const int kloc = kh * 4;
                wb[(kloc+0)*128 + sBase] = pf.x;
                wb[(kloc+1)*128 + sBase] = pf.y;
                wb[(kloc+2)*128 + sBase] = pf.z;
                wb[(kloc+3)*128 + sBase] = pf.w;
                __syncthreads();

                // prefetch next stage (overlaps with compute below)
                int sn = s + 1;
                if (sn < NST) {
                    if (sn < NST_X)
                        pf = *(const float4*)(Wih + row_st*EMBD + sn*KT + kh*4);
                    else
                        pf = *(const float4*)(Whh + row_st*HIDD + (sn - NST_X)*KT + kh*4);
                }

                // A-operand row pointers for this stage (warp-uniform -> smem broadcast)
                const float *ar0, *ar1, *ar2, *ar3;
                if (s < NST_X) {
                    const float* base = xt_s + s*KT;
                    ar0 = base + (warp*4+0)*EMBD; ar1 = base + (warp*4+1)*EMBD;
                    ar2 = base + (warp*4+2)*EMBD; ar3 = base + (warp*4+3)*EMBD;
                } else {
                    const float* base = hc + (s - NST_X)*KT;
                    ar0 = base + (warp*4+0)*HIDD; ar1 = base + (warp*4+1)*HIDD;
                    ar2 = base + (warp*4+2)*HIDD; ar3 = base + (warp*4+3)*HIDD;
                }

                #pragma unroll
                for (int k2 = 0; k2 < KT/2; ++k2) {
                    float2 a0 = *(const float2*)(ar0 + 2*k2);
                    float2 a1 = *(const float2*)(ar1 + 2*k2);
                    float2 a2 = *(const float2*)(ar2 + 2*k2);
                    float2 a3 = *(const float2*)(ar3 + 2*k2);
                    GSTEP(2*k2,     a0.x, a1.x, a2.x, a3.x);
                    GSTEP(2*k2 + 1, a0.y, a1.y, a2.y, a3.y);
                }
            }

            // ---- LSTM cell update for this chunk's (word, hid) elements ----
            {
                int j = j0 + lane;
                #pragma unroll
                for (int wi = 0; wi < 4; ++wi) {
                    int w = warp*4 + wi;
                    float vi, vf, vg, vo;
                    upk2(vi, vf, accIF[wi]);
                    upk2(vg, vo, accGO[wi]);
                    float iv = fsigm(vi);
                    float fv = fsigm(vf);
                    float gv = ftanh_(vg);
                    float ov = fsigm(vo);
                    float cold = c_s[w*HIDD + j];
                    float cnew = fmaf(fv, cold, iv * gv);
                    float hnew = ov * ftanh_(cnew);
                    bool m = (t < len_s[w]);
                    c_s[w*HIDD + j] = m ? cnew : cold;
                    hn[w*HIDD + j]  = m ? hnew : hc[w*HIDD + j];
                }
            }
        }
        cur ^= 1;
        __syncthreads();
    }

    // ---- write final h (concat layout: [w, dir*256 + j]) ----
    const float* hf = h_s + cur*(BW*HIDD);
    for (int idx = tid; idx < BW*HIDD; idx += NTHREADS) {
        int w = idx >> 8, j = idx & 255;
        out[(w0 + w)*(2*HIDD) + dir*HIDD + j] = hf[idx];
    }
}

extern "C" void kernel_launch(void* const* d_in, const int* in_sizes, int n_in,
                              void* d_out, int out_size)
{
    const int*   char_ids = (const int*)  d_in[0];
    const int*   lengths  = (const int*)  d_in[1];
    const float* emb      = (const float*)d_in[2];
    const float* Wih_f    = (const float*)d_in[3];
    const float* Whh_f    = (const float*)d_in[4];
    const float* bih_f    = (const float*)d_in[5];
    const float* bhh_f    = (const float*)d_in[6];
    const float* Wih_b    = (const float*)d_in[7];
    const float* Whh_b    = (const float*)d_in[8];
    const float* bih_b    = (const float*)d_in[9];
    const float* bhh_b    = (const float*)d_in[10];
    float* out = (float*)d_out;

    cudaFuncSetAttribute(bilstm_kernel,
                         cudaFuncAttributeMaxDynamicSharedMemorySize, SMEM_BYTES);

    dim3 grid(NW / BW, 2);
    bilstm_kernel<<<grid, NTHREADS, SMEM_BYTES>>>(
        char_ids, lengths, emb,
        Wih_f, Whh_f, bih_f, bhh_f,
        Wih_b, Whh_b, bih_b, bhh_b,
        out);
}

// round 15
// speedup vs baseline: 1.3668x; 1.3168x over previous
#include <cuda_runtime.h>

#define NW       16384
#define MAXLEN   16
#define EMBD     64
#define HIDD     256
#define VOCAB    128
#define BW       64          // words per block
#define NTHREADS 512
#define KT       32          // K-tile per stage (h-part only)
#define NST      (HIDD/KT)   // 8 stages

// smem (floats): h double buffer + c + W double-buffer stage; + lengths + ids (ints)
#define SMEM_FLOATS (2*BW*HIDD + BW*HIDD + 2*KT*128)
#define SMEM_BYTES  (SMEM_FLOATS*4 + 2*BW*4)

// precomputed per-vocab gate contributions: [dir][v][j][gate], gate=(i,f,g,o)
__device__ float g_gemb[2*VOCAB*HIDD*4];

__device__ __forceinline__ float fsigm(float x) {
    return __fdividef(1.0f, 1.0f + __expf(-x));
}
__device__ __forceinline__ float ftanh_(float x) {
    return __fdividef(2.0f, 1.0f + __expf(-2.0f * x)) - 1.0f;
}

// ---- fp32x2 (FFMA2) helpers ----
__device__ __forceinline__ unsigned long long pk2(float lo, float hi) {
    unsigned long long r;
    asm("mov.b64 %0, {%1, %2};" : "=l"(r) : "f"(lo), "f"(hi));
    return r;
}
__device__ __forceinline__ unsigned long long dup2(float v) {
    unsigned long long r;
    asm("mov.b64 %0, {%1, %1};" : "=l"(r) : "f"(v));
    return r;
}
__device__ __forceinline__ void fma2(unsigned long long& acc,
                                     unsigned long long a,
                                     unsigned long long b) {
    asm("fma.rn.f32x2 %0, %1, %2, %0;" : "+l"(acc) : "l"(a), "l"(b));
}
__device__ __forceinline__ void upk2(float& lo, float& hi, unsigned long long v) {
    asm("mov.b64 {%0, %1}, %2;" : "=f"(lo), "=f"(hi) : "l"(v));
}

// One k-step: LDS.128 pulls (i,f,g,o) weight quad for this lane; two FFMA2 per word.
#define GSTEP(KK, AV0, AV1, AV2, AV3)                                          \
    {                                                                          \
        const ulonglong2 wp =                                                  \
            *(const ulonglong2*)(wb + (KK)*128 + lane4);                       \
        unsigned long long ad;                                                 \
        ad = dup2(AV0); fma2(accIF[0], ad, wp.x); fma2(accGO[0], ad, wp.y);    \
        ad = dup2(AV1); fma2(accIF[1], ad, wp.x); fma2(accGO[1], ad, wp.y);    \
        ad = dup2(AV2); fma2(accIF[2], ad, wp.x); fma2(accGO[2], ad, wp.y);    \
        ad = dup2(AV3); fma2(accIF[3], ad, wp.x); fma2(accGO[3], ad, wp.y);    \
    }

// ---- kernel 1: build gemb = W_ih @ emb^T + (b_ih + b_hh) ----
__global__ __launch_bounds__(256)
void gemb_kernel(const float* __restrict__ emb,
                 const float* __restrict__ Wih_f, const float* __restrict__ bih_f,
                 const float* __restrict__ bhh_f,
                 const float* __restrict__ Wih_b, const float* __restrict__ bih_b,
                 const float* __restrict__ bhh_b)
{
    __shared__ float ev[EMBD];
    const int dir = blockIdx.x >> 7;
    const int v   = blockIdx.x & (VOCAB - 1);
    const float* Wih = dir ? Wih_b : Wih_f;
    const float* bih = dir ? bih_b : bih_f;
    const float* bhh = dir ? bhh_b : bhh_f;
    const int j = threadIdx.x;                 // 0..255 = hidden index
    if (j < EMBD) ev[j] = emb[v*EMBD + j];
    __syncthreads();

    float4 r;
    float* rp = (float*)&r;
    #pragma unroll
    for (int g = 0; g < 4; ++g) {
        int row = g*HIDD + j;
        float s = bih[row] + bhh[row];
        const float* wr = Wih + row*EMBD;
        #pragma unroll 16
        for (int k = 0; k < EMBD; ++k) s = fmaf(wr[k], ev[k], s);
        rp[g] = s;
    }
    *(float4*)(g_gemb + ((dir*VOCAB + v)*HIDD + j)*4) = r;
}

// ---- kernel 2: recurrent part (K = 256, h @ W_hh only) ----
__global__ __launch_bounds__(NTHREADS, 1)
void bilstm_kernel(const int*   __restrict__ char_ids,
                   const int*   __restrict__ lengths,
                   const float* __restrict__ Whh_f,
                   const float* __restrict__ Whh_b,
                   float* __restrict__ out)
{
    extern __shared__ float sm[];
    float* h_s  = sm;                        // [2][BW][HIDD]
    float* c_s  = h_s + 2*BW*HIDD;           // [BW][HIDD]
    float* W_s  = c_s + BW*HIDD;             // [2][KT][128]  ([k][lane][gate])
    int*   len_s = (int*)(W_s + 2*KT*128);   // [BW]
    int*   ids_s = len_s + BW;               // [BW] char id at current t

    const int tid   = threadIdx.x;
    const int lane  = tid & 31;
    const int lane4 = lane * 4;
    const int warp  = tid >> 5;              // 16 warps, each owns 4 words
    const int dir   = blockIdx.y;
    const int w0    = blockIdx.x * BW;

    const float* Whh = dir ? Whh_b : Whh_f;

    // ---- init ----
    for (int i = tid; i < BW; i += NTHREADS) len_s[i] = lengths[w0 + i];
    for (int i = tid; i < 2*BW*HIDD; i += NTHREADS) h_s[i] = 0.0f;
    for (int i = tid; i < BW*HIDD;   i += NTHREADS) c_s[i] = 0.0f;
    __syncthreads();
    // char ids for t=0 (needs len_s for backward dir)
    if (tid < BW) {
        int L = len_s[tid];
        int te = dir ? (L - 1) : 0;
        ids_s[tid] = char_ids[(w0 + tid)*MAXLEN + te];
    }
    __syncthreads();

    // weight staging: rIdx = tid&127 selects (gate,i) with g = rIdx&3, i = rIdx>>2
    // -> smem column sBase = i*4 + g == rIdx  => warp-consecutive STS (no conflicts)
    const int rIdx = tid & 127;
    const int kh   = tid >> 7;               // 0..3, owns k sub-range kh*8..kh*8+7
    const int g_st = rIdx & 3;
    const int i_st = rIdx >> 2;

    int cur = 0;
    for (int t = 0; t < MAXLEN; ++t) {
        const float* hc = h_s + cur*(BW*HIDD);
        float*       hn = h_s + (cur^1)*(BW*HIDD);

        for (int chunk = 0; chunk < 8; ++chunk) {
            const int j0 = chunk * 32;
            const int row_st = g_st*HIDD + j0 + i_st;   // weight row this thread stages

            // accumulators init from precomputed x-part + bias (L2-resident gemb)
            unsigned long long accIF[4], accGO[4];
            {
                int j = j0 + lane;
                #pragma unroll
                for (int wi = 0; wi < 4; ++wi) {
                    int w = warp*4 + wi;
                    int v = ids_s[w];
                    float4 q = *(const float4*)(g_gemb + (((dir<<7) + v)*HIDD + j)*4);
                    accIF[wi] = pk2(q.x, q.y);
                    accGO[wi] = pk2(q.z, q.w);
                }
            }

            // prefetch stage 0 weights (two float4 = 8 k-values of one row)
            float4 pf0 = *(const float4*)(Whh + row_st*HIDD + kh*8);
            float4 pf1 = *(const float4*)(Whh + row_st*HIDD + kh*8 + 4);

            for (int s = 0; s < NST; ++s) {
                // commit prefetched k-slab to smem buffer s&1
                float* wb = W_s + (s & 1)*(KT*128);
                const int kloc = kh * 8;
                wb[(kloc+0)*128 + rIdx] = pf0.x;
                wb[(kloc+1)*128 + rIdx] = pf0.y;
                wb[(kloc+2)*128 + rIdx] = pf0.z;
                wb[(kloc+3)*128 + rIdx] = pf0.w;
                wb[(kloc+4)*128 + rIdx] = pf1.x;
                wb[(kloc+5)*128 + rIdx] = pf1.y;
                wb[(kloc+6)*128 + rIdx] = pf1.z;
                wb[(kloc+7)*128 + rIdx] = pf1.w;
                __syncthreads();

                // prefetch next stage (overlaps with compute below)
                int sn = s + 1;
                if (sn < NST) {
                    pf0 = *(const float4*)(Whh + row_st*HIDD + sn*KT + kh*8);
                    pf1 = *(const float4*)(Whh + row_st*HIDD + sn*KT + kh*8 + 4);
                }

                // A-operand row pointers (warp-uniform -> smem broadcast)
                const float* base = hc + s*KT;
                const float* ar0 = base + (warp*4+0)*HIDD;
                const float* ar1 = base + (warp*4+1)*HIDD;
                const float* ar2 = base + (warp*4+2)*HIDD;
                const float* ar3 = base + (warp*4+3)*HIDD;

                #pragma unroll
                for (int k2 = 0; k2 < KT/2; ++k2) {
                    float2 a0 = *(const float2*)(ar0 + 2*k2);
                    float2 a1 = *(const float2*)(ar1 + 2*k2);
                    float2 a2 = *(const float2*)(ar2 + 2*k2);
                    float2 a3 = *(const float2*)(ar3 + 2*k2);
                    GSTEP(2*k2,     a0.x, a1.x, a2.x, a3.x);
                    GSTEP(2*k2 + 1, a0.y, a1.y, a2.y, a3.y);
                }
            }

            // ---- LSTM cell update for this chunk's (word, hid) elements ----
            {
                int j = j0 + lane;
                #pragma unroll
                for (int wi = 0; wi < 4; ++wi) {
                    int w = warp*4 + wi;
                    float vi, vf, vg, vo;
                    upk2(vi, vf, accIF[wi]);
                    upk2(vg, vo, accGO[wi]);
                    float iv = fsigm(vi);
                    float fv = fsigm(vf);
                    float gv = ftanh_(vg);
                    float ov = fsigm(vo);
                    float cold = c_s[w*HIDD + j];
                    float cnew = fmaf(fv, cold, iv * gv);
                    float hnew = ov * ftanh_(cnew);
                    bool m = (t < len_s[w]);
                    c_s[w*HIDD + j] = m ? cnew : cold;
                    hn[w*HIDD + j]  = m ? hnew : hc[w*HIDD + j];
                }
            }
        }

        // prep char ids for next t (safe: all ids_s reads for this t are behind
        // the chunk-7 stage barriers every thread has already passed)
        if (tid < BW && t + 1 < MAXLEN) {
            int L = len_s[tid];
            int te = dir ? max(L - 2 - t, 0) : (t + 1);
            ids_s[tid] = char_ids[(w0 + tid)*MAXLEN + te];
        }
        cur ^= 1;
        __syncthreads();
    }

    // ---- write final h (concat layout: [w, dir*256 + j]) ----
    const float* hf = h_s + cur*(BW*HIDD);
    for (int idx = tid; idx < BW*HIDD; idx += NTHREADS) {
        int w = idx >> 8, j = idx & 255;
        out[(w0 + w)*(2*HIDD) + dir*HIDD + j] = hf[idx];
    }
}

extern "C" void kernel_launch(void* const* d_in, const int* in_sizes, int n_in,
                              void* d_out, int out_size)
{
    const int*   char_ids = (const int*)  d_in[0];
    const int*   lengths  = (const int*)  d_in[1];
    const float* emb      = (const float*)d_in[2];
    const float* Wih_f    = (const float*)d_in[3];
    const float* Whh_f    = (const float*)d_in[4];
    const float* bih_f    = (const float*)d_in[5];
    const float* bhh_f    = (const float*)d_in[6];
    const float* Wih_b    = (const float*)d_in[7];
    const float* Whh_b    = (const float*)d_in[8];
    const float* bih_b    = (const float*)d_in[9];
    const float* bhh_b    = (const float*)d_in[10];
    float* out = (float*)d_out;

    cudaFuncSetAttribute(bilstm_kernel,
                         cudaFuncAttributeMaxDynamicSharedMemorySize, SMEM_BYTES);

    gemb_kernel<<<2*VOCAB, 256>>>(emb, Wih_f, bih_f, bhh_f, Wih_b, bih_b, bhh_b);

    dim3 grid(NW / BW, 2);
    bilstm_kernel<<<grid, NTHREADS, SMEM_BYTES>>>(
        char_ids, lengths, Whh_f, Whh_b, out);
}